// round 6
// baseline (speedup 1.0000x reference)
#include <cuda_runtime.h>
#include <math.h>

#define SC 64
#define VC 32
#define DIMF 160
#define NB 64
#define TBL 4096
#define CUTOFF_F 5.0f
#define TILE_N 64       // nodes per finalize block (32 pairs)
#define SROW 70         // sA2 row stride in words (even -> 8B aligned pairs)

__device__ float g_table[TBL];
__device__ double g_ewsum;

// ---- f32x2 packed helpers (FFMA2 path, sm_103a) ----
__device__ __forceinline__ unsigned long long pack2(float x) {
    unsigned long long r;
    unsigned int u = __float_as_uint(x);
    asm("mov.b64 %0, {%1, %1};" : "=l"(r) : "r"(u));
    return r;
}
__device__ __forceinline__ void ffma2(unsigned long long& d,
                                      unsigned long long a,
                                      unsigned long long b) {
    asm("fma.rn.f32x2 %0, %1, %2, %0;" : "+l"(d) : "l"(a), "l"(b));
}
__device__ __forceinline__ float2 unpk(unsigned long long v) {
    unsigned int lo, hi;
    asm("mov.b64 {%0, %1}, %2;" : "=r"(lo), "=r"(hi) : "l"(v));
    return make_float2(__uint_as_float(lo), __uint_as_float(hi));
}

// Tabulate t(d) = sigmoid( cut(d) * sum_b exp(-0.5*((d-c_b)/w_b)^2) * pw_b + pb )
__global__ void k_build_table(const float* __restrict__ centers,
                              const float* __restrict__ widths,
                              const float* __restrict__ pw,
                              const float* __restrict__ pb) {
    int i = blockIdx.x * blockDim.x + threadIdx.x;
    if (i == 0) g_ewsum = 0.0;
    if (i >= TBL) return;
    float d = CUTOFF_F * (float)i / (float)(TBL - 1);
    float acc = 0.f;
#pragma unroll 8
    for (int b = 0; b < NB; b++) {
        float z = (d - centers[b]) / widths[b];
        acc += expf(-0.5f * z * z) * pw[b];
    }
    float cut = 0.5f * (cosf(3.14159265358979323846f * d / CUTOFF_F) + 1.0f);
    float t = acc * cut + pb[0];
    g_table[i] = 1.0f / (1.0f + expf(-t));
}

__global__ void k_edge_w(const int* __restrict__ ei,
                         const float* __restrict__ pos, int E) {
    int e = blockIdx.x * blockDim.x + threadIdx.x;
    float v = 0.f;
    if (e < E) {
        int s = ei[e];
        int d = ei[E + e];
        float dx = pos[3*s+0] - pos[3*d+0];
        float dy = pos[3*s+1] - pos[3*d+1];
        float dz = pos[3*s+2] - pos[3*d+2];
        float dist = sqrtf(dx*dx + dy*dy + dz*dz);
        float u = fminf(dist, CUTOFF_F) * ((float)(TBL - 1) / CUTOFF_F);
        int i0 = (int)u;
        if (i0 > TBL - 2) i0 = TBL - 2;
        float f = u - (float)i0;
        float t0 = g_table[i0];
        float t1 = g_table[i0 + 1];
        v = t0 + f * (t1 - t0);
    }
#pragma unroll
    for (int o = 16; o > 0; o >>= 1) v += __shfl_down_sync(0xffffffffu, v, o);
    __shared__ float ws[8];
    int lane = threadIdx.x & 31, w = threadIdx.x >> 5;
    if (lane == 0) ws[w] = v;
    __syncthreads();
    if (threadIdx.x < 8) {
        v = ws[threadIdx.x];
#pragma unroll
        for (int o = 4; o > 0; o >>= 1) v += __shfl_down_sync(0xffu, v, o);
        if (threadIdx.x == 0) atomicAdd(&g_ewsum, (double)v);
    }
}

// Scatter-add raw x[src] rows into out[dst] — LTS-roofline-bound, leave alone.
__global__ void k_scatter(const int* __restrict__ ei,
                          const float* __restrict__ x,
                          float* __restrict__ out, int E) {
    __shared__ int ss[32], sd[32];
    int base = blockIdx.x * 32;
    int t = threadIdx.x;
    if (t < 32) {
        int e = base + t;
        ss[t] = (e < E) ? ei[e] : 0;
    } else if (t < 64) {
        int e = base + t - 32;
        sd[t - 32] = (e < E) ? ei[E + e] : 0;
    }
    __syncthreads();
#pragma unroll
    for (int it = 0; it < 5; it++) {
        int j = t + it * 256;
        int el = j / 40;
        int k = j - el * 40;
        if (base + el >= E) continue;
        float4 v = *reinterpret_cast<const float4*>(x + (size_t)ss[el] * DIMF + k * 4);
        float* dp = out + (size_t)sd[el] * DIMF + k * 4;
        asm volatile("red.global.add.v4.f32 [%0], {%1, %2, %3, %4};"
                     :: "l"(dp), "f"(v.x), "f"(v.y), "f"(v.z), "f"(v.w)
                     : "memory");
    }
}

// Finalize with node-pair FFMA2.
// 64 nodes/block, 256 threads: thread (tn = t/8, tc = t%8) computes nodes
// {2tn, 2tn+1} packed in f32x2 lanes, for scalar cols {4tc..+4, 32+4tc..+4}
// and vector cols 64+12tc..+12.
// Dynamic smem layout:
//   sA2   : float [DIMF][SROW]  (activations, [channel][node])   44800 B
//   W0q   : ull   [SC][4][8][2] (pre-duplicated W0 pairs)        32768 B
//   W1q   : ull   [VC][2][8][2]                                   8192 B
#define OFF_W0Q 44800
#define OFF_W1Q 77568
#define SMEM_FIN 85760

__global__ void __launch_bounds__(256) k_finalize(
        float* __restrict__ out,
        const float* __restrict__ W0,
        const float* __restrict__ W1,
        const float* __restrict__ gamma,
        const float* __restrict__ beta,
        int N, int E) {
    extern __shared__ char smem[];
    float* sA2 = reinterpret_cast<float*>(smem);
    unsigned long long* W0q = reinterpret_cast<unsigned long long*>(smem + OFF_W0Q);
    unsigned long long* W1q = reinterpret_cast<unsigned long long*>(smem + OFF_W1Q);

    int t  = threadIdx.x;
    int tn = t >> 3;          // pair id 0..31
    int tc = t & 7;
    int base = blockIdx.x * TILE_N;
    int pn2 = 2 * tn;

    // Stage W0 packed: W0q[k][m][tcx][slot]; m = half*2 + (q>>1), slot = q&1
    for (int i = t; i < SC * SC; i += 256) {
        int k = i >> 6, col = i & 63;
        int half = col >> 5, cl = col & 31;
        int tcx = cl >> 2, q = cl & 3;
        W0q[((k * 4 + half * 2 + (q >> 1)) * 8 + tcx) * 2 + (q & 1)] = pack2(W0[i]);
    }
    for (int i = t; i < VC * VC; i += 256) {
        int c = i >> 5, col = i & 31;
        int tcx = col >> 2, q = col & 3;
        W1q[((c * 2 + (q >> 1)) * 8 + tcx) * 2 + (q & 1)] = pack2(W1[i]);
    }
    // Stage activations transposed: sA2[c][r], coalesced LDG over c
    for (int j = t; j < TILE_N * DIMF; j += 256) {
        int r = j / DIMF, c = j - r * DIMF;
        int n = base + r;
        sA2[c * SROW + r] = (n < N) ? out[(size_t)n * DIMF + c] : 0.f;
    }

    // Per-thread params (overlap with staging)
    float ew  = (float)(g_ewsum / (double)E);
    float ews = ew * 0.125f;
    float ewv = ew * 0.17677669529663689f;
    float4 gl = *reinterpret_cast<const float4*>(gamma + tc * 4);
    float4 gh = *reinterpret_cast<const float4*>(gamma + 32 + tc * 4);
    float4 bl = *reinterpret_cast<const float4*>(beta + tc * 4);
    float4 bh = *reinterpret_cast<const float4*>(beta + 32 + tc * 4);

    __syncthreads();

    // ---- scalar path: 8 node-pair accumulators ----
    unsigned long long acc[8];
#pragma unroll
    for (int q = 0; q < 8; q++) acc[q] = 0ull;
#pragma unroll 8
    for (int k = 0; k < SC; k++) {
        unsigned long long a2 =
            *reinterpret_cast<const unsigned long long*>(&sA2[k * SROW + pn2]);
        const unsigned long long* wr = &W0q[(k * 4) * 16 + tc * 2];
        ulonglong2 w0 = *reinterpret_cast<const ulonglong2*>(wr);
        ulonglong2 w1 = *reinterpret_cast<const ulonglong2*>(wr + 16);
        ulonglong2 w2 = *reinterpret_cast<const ulonglong2*>(wr + 32);
        ulonglong2 w3 = *reinterpret_cast<const ulonglong2*>(wr + 48);
        ffma2(acc[0], a2, w0.x); ffma2(acc[1], a2, w0.y);
        ffma2(acc[2], a2, w1.x); ffma2(acc[3], a2, w1.y);
        ffma2(acc[4], a2, w2.x); ffma2(acc[5], a2, w2.y);
        ffma2(acc[6], a2, w3.x); ffma2(acc[7], a2, w3.y);
    }

    // ---- vector path: 12 node-pair accumulators (q=dch-4tc, j) ----
    unsigned long long vacc[12];
#pragma unroll
    for (int q = 0; q < 12; q++) vacc[q] = 0ull;
#pragma unroll 8
    for (int c = 0; c < VC; c++) {
        unsigned long long a0 =
            *reinterpret_cast<const unsigned long long*>(&sA2[(SC + 3*c + 0) * SROW + pn2]);
        unsigned long long a1 =
            *reinterpret_cast<const unsigned long long*>(&sA2[(SC + 3*c + 1) * SROW + pn2]);
        unsigned long long a2v =
            *reinterpret_cast<const unsigned long long*>(&sA2[(SC + 3*c + 2) * SROW + pn2]);
        const unsigned long long* wr = &W1q[(c * 2) * 16 + tc * 2];
        ulonglong2 wa = *reinterpret_cast<const ulonglong2*>(wr);
        ulonglong2 wb = *reinterpret_cast<const ulonglong2*>(wr + 16);
        ffma2(vacc[0], a0, wa.x);  ffma2(vacc[1],  a1, wa.x);  ffma2(vacc[2],  a2v, wa.x);
        ffma2(vacc[3], a0, wa.y);  ffma2(vacc[4],  a1, wa.y);  ffma2(vacc[5],  a2v, wa.y);
        ffma2(vacc[6], a0, wb.x);  ffma2(vacc[7],  a1, wb.x);  ffma2(vacc[8],  a2v, wb.x);
        ffma2(vacc[9], a0, wb.y);  ffma2(vacc[10], a1, wb.y);  ffma2(vacc[11], a2v, wb.y);
    }

    // ---- LN stats for both nodes over the 8 tc-lanes ----
    float2 sc[8];
    float s1a = 0.f, s2a = 0.f, s1b = 0.f, s2b = 0.f;
#pragma unroll
    for (int q = 0; q < 8; q++) {
        float2 f = unpk(acc[q]);
        f.x *= ews; f.y *= ews;
        sc[q] = f;
        s1a += f.x; s2a += f.x * f.x;
        s1b += f.y; s2b += f.y * f.y;
    }
#pragma unroll
    for (int o = 1; o < 8; o <<= 1) {
        s1a += __shfl_xor_sync(0xffffffffu, s1a, o);
        s2a += __shfl_xor_sync(0xffffffffu, s2a, o);
        s1b += __shfl_xor_sync(0xffffffffu, s1b, o);
        s2b += __shfl_xor_sync(0xffffffffu, s2b, o);
    }
    float muA = s1a * (1.0f / SC), vA = s2a * (1.0f / SC) - muA * muA;
    float muB = s1b * (1.0f / SC), vB = s2b * (1.0f / SC) - muB * muB;
    float rA = rsqrtf(vA + 1e-5f), rB = rsqrtf(vB + 1e-5f);

    const float* g4l = &gl.x; const float* g4h = &gh.x;
    const float* b4l = &bl.x; const float* b4h = &bh.x;

#pragma unroll
    for (int nn = 0; nn < 2; nn++) {
        int n = base + pn2 + nn;
        if (n >= N) break;
        float mu = nn ? muB : muA;
        float rs = nn ? rB : rA;
        float* orow = out + (size_t)n * DIMF;
        float o8[8];
#pragma unroll
        for (int q = 0; q < 8; q++) {
            float v = nn ? sc[q].y : sc[q].x;
            float gq = (q < 4) ? g4l[q] : g4h[q - 4];
            float bq = (q < 4) ? b4l[q] : b4h[q - 4];
            float xln = (v - mu) * rs * gq + bq;
            o8[q] = xln / (1.f + expf(-xln));
        }
        *reinterpret_cast<float4*>(orow + tc * 4) =
            make_float4(o8[0], o8[1], o8[2], o8[3]);
        *reinterpret_cast<float4*>(orow + 32 + tc * 4) =
            make_float4(o8[4], o8[5], o8[6], o8[7]);
        float* ov = orow + SC + tc * 12;
#pragma unroll
        for (int g = 0; g < 3; g++) {
            float v0 = (nn ? unpk(vacc[4*g+0]).y : unpk(vacc[4*g+0]).x) * ewv;
            float v1 = (nn ? unpk(vacc[4*g+1]).y : unpk(vacc[4*g+1]).x) * ewv;
            float v2 = (nn ? unpk(vacc[4*g+2]).y : unpk(vacc[4*g+2]).x) * ewv;
            float v3 = (nn ? unpk(vacc[4*g+3]).y : unpk(vacc[4*g+3]).x) * ewv;
            *reinterpret_cast<float4*>(ov + 4 * g) = make_float4(v0, v1, v2, v3);
        }
    }
}

extern "C" void kernel_launch(void* const* d_in, const int* in_sizes, int n_in,
                              void* d_out, int out_size) {
    const float* x       = (const float*)d_in[0];
    const float* pos     = (const float*)d_in[1];
    const int*   ei      = (const int*)d_in[2];   // int32 (JAX x64 disabled)
    // d_in[3] = edge_rand: unused (rotation cancels algebraically)
    const float* W0      = (const float*)d_in[4];
    const float* W1      = (const float*)d_in[5];
    const float* centers = (const float*)d_in[6];
    const float* widths  = (const float*)d_in[7];
    const float* pw      = (const float*)d_in[8];
    const float* pb      = (const float*)d_in[9];
    const float* gamma   = (const float*)d_in[10];
    const float* beta    = (const float*)d_in[11];
    float* out = (float*)d_out;

    int N = in_sizes[0] / DIMF;
    int E = in_sizes[2] / 2;

    static int smem_set = 0;
    if (!smem_set) {
        cudaFuncSetAttribute(k_finalize,
                             cudaFuncAttributeMaxDynamicSharedMemorySize, SMEM_FIN);
        smem_set = 1;
    }

    cudaMemsetAsync(out, 0, (size_t)N * DIMF * sizeof(float), 0);
    k_build_table<<<(TBL + 255) / 256, 256>>>(centers, widths, pw, pb);
    k_edge_w<<<(E + 255) / 256, 256>>>(ei, pos, E);
    k_scatter<<<(E + 31) / 32, 256>>>(ei, x, out, E);
    k_finalize<<<(N + TILE_N - 1) / TILE_N, 256, SMEM_FIN>>>(out, W0, W1, gamma, beta, N, E);
}

// round 7
// speedup vs baseline: 1.0881x; 1.0881x over previous
#include <cuda_runtime.h>
#include <math.h>

#define SC 64
#define VC 32
#define DIMF 160
#define NB 64
#define TBL 4096
#define CUTOFF_F 5.0f
#define TILE_N 32       // nodes per finalize block

__device__ float g_table[TBL];
__device__ double g_ewsum;

// Tabulate t(d) = sigmoid( cut(d) * sum_b exp(-0.5*((d-c_b)/w_b)^2) * pw_b + pb )
// Thread 0 zeroes the edge-weight accumulator (runs before k_scatter).
__global__ void k_build_table(const float* __restrict__ centers,
                              const float* __restrict__ widths,
                              const float* __restrict__ pw,
                              const float* __restrict__ pb) {
    int i = blockIdx.x * blockDim.x + threadIdx.x;
    if (i == 0) g_ewsum = 0.0;
    if (i >= TBL) return;
    float d = CUTOFF_F * (float)i / (float)(TBL - 1);
    float acc = 0.f;
#pragma unroll 8
    for (int b = 0; b < NB; b++) {
        float z = (d - centers[b]) / widths[b];
        acc += expf(-0.5f * z * z) * pw[b];
    }
    float cut = 0.5f * (cosf(3.14159265358979323846f * d / CUTOFF_F) + 1.0f);
    float t = acc * cut + pb[0];
    g_table[i] = 1.0f / (1.0f + expf(-t));
}

// Scatter-add raw x[src] rows (40 float4) into out[dst], with the per-edge
// weight computation fused in (warp 0 computes 32 edge weights via table lerp,
// overlapped with the LTS-bound RED traffic of the other warps).
__global__ void k_scatter(const int* __restrict__ ei,
                          const float* __restrict__ x,
                          const float* __restrict__ pos,
                          float* __restrict__ out, int E) {
    __shared__ int ss[32], sd[32];
    int base = blockIdx.x * 32;
    int t = threadIdx.x;
    if (t < 32) {
        int e = base + t;
        ss[t] = (e < E) ? ei[e] : 0;
    } else if (t < 64) {
        int e = base + t - 32;
        sd[t - 32] = (e < E) ? ei[E + e] : 0;
    }
    __syncthreads();

    // Fused edge weight (warp 0 only)
    if (t < 32) {
        float v = 0.f;
        int e = base + t;
        if (e < E) {
            int s = ss[t], d = sd[t];
            float dx = pos[3*s+0] - pos[3*d+0];
            float dy = pos[3*s+1] - pos[3*d+1];
            float dz = pos[3*s+2] - pos[3*d+2];
            float dist = sqrtf(dx*dx + dy*dy + dz*dz);
            float u = fminf(dist, CUTOFF_F) * ((float)(TBL - 1) / CUTOFF_F);
            int i0 = (int)u;
            if (i0 > TBL - 2) i0 = TBL - 2;
            float f = u - (float)i0;
            float t0 = g_table[i0];
            float t1 = g_table[i0 + 1];
            v = t0 + f * (t1 - t0);
        }
#pragma unroll
        for (int o = 16; o > 0; o >>= 1) v += __shfl_down_sync(0xffffffffu, v, o);
        if (t == 0) atomicAdd(&g_ewsum, (double)v);
    }

#pragma unroll
    for (int it = 0; it < 5; it++) {
        int j = t + it * 256;          // 0..1279 = 32 edges * 40 float4
        int el = j / 40;
        int k = j - el * 40;
        if (base + el >= E) continue;
        float4 v = *reinterpret_cast<const float4*>(x + (size_t)ss[el] * DIMF + k * 4);
        float* dp = out + (size_t)sd[el] * DIMF + k * 4;
        asm volatile("red.global.add.v4.f32 [%0], {%1, %2, %3, %4};"
                     :: "l"(dp), "f"(v.x), "f"(v.y), "f"(v.z), "f"(v.w)
                     : "memory");
    }
}

// Tiled finalize: 32 nodes/block, W0+W1 in shared, thread (tn=t/8, tc=t%8)
// computes node tn's scalar cols {4tc..+4, 32+4tc..+4} and vector cols
// 64+12tc..+12. minBlocks=5 forces regs<=51 for 40 warps/SM.
__global__ void __launch_bounds__(256, 5) k_finalize(
        float* __restrict__ out,
        const float* __restrict__ W0,
        const float* __restrict__ W1,
        const float* __restrict__ gamma,
        const float* __restrict__ beta,
        int N, int E) {
    __shared__ float sA[TILE_N][164];      // 164-pad: distinct banks per tn
    __shared__ float W0sh[SC][SC];
    __shared__ float W1sh[VC][VC];

    int t  = threadIdx.x;
    int tn = t >> 3;
    int tc = t & 7;
    int base = blockIdx.x * TILE_N;
    int n = base + tn;

    for (int i = t; i < SC * SC; i += 256) W0sh[i >> 6][i & 63] = W0[i];
    for (int i = t; i < VC * VC; i += 256) W1sh[i >> 5][i & 31] = W1[i];

    for (int j = t; j < TILE_N * (DIMF / 4); j += 256) {
        int r  = j / 40;
        int c4 = j - r * 40;
        float4 v = make_float4(0.f, 0.f, 0.f, 0.f);
        int nr = base + r;
        if (nr < N) v = *reinterpret_cast<const float4*>(out + (size_t)nr * DIMF + c4 * 4);
        *reinterpret_cast<float4*>(&sA[r][c4 * 4]) = v;
    }

    float ew  = (float)(g_ewsum / (double)E);
    float ews = ew * 0.125f;
    float ewv = ew * 0.17677669529663689f;
    float4 gl = *reinterpret_cast<const float4*>(gamma + tc * 4);
    float4 gh = *reinterpret_cast<const float4*>(gamma + 32 + tc * 4);
    float4 bl = *reinterpret_cast<const float4*>(beta + tc * 4);
    float4 bh = *reinterpret_cast<const float4*>(beta + 32 + tc * 4);

    __syncthreads();

    // ---- scalar path: 8 accumulators ----
    float as[8];
#pragma unroll
    for (int q = 0; q < 8; q++) as[q] = 0.f;
#pragma unroll
    for (int k = 0; k < SC; k += 4) {
        float4 a4 = *reinterpret_cast<const float4*>(&sA[tn][k]);
        float av[4] = {a4.x, a4.y, a4.z, a4.w};
#pragma unroll
        for (int kk = 0; kk < 4; kk++) {
            float4 wl = *reinterpret_cast<const float4*>(&W0sh[k + kk][tc * 4]);
            float4 wh = *reinterpret_cast<const float4*>(&W0sh[k + kk][32 + tc * 4]);
            float a = av[kk];
            as[0] = fmaf(a, wl.x, as[0]);
            as[1] = fmaf(a, wl.y, as[1]);
            as[2] = fmaf(a, wl.z, as[2]);
            as[3] = fmaf(a, wl.w, as[3]);
            as[4] = fmaf(a, wh.x, as[4]);
            as[5] = fmaf(a, wh.y, as[5]);
            as[6] = fmaf(a, wh.z, as[6]);
            as[7] = fmaf(a, wh.w, as[7]);
        }
    }

    // ---- vector path: 12 accumulators ----
    float avv[12];
#pragma unroll
    for (int q = 0; q < 12; q++) avv[q] = 0.f;
#pragma unroll
    for (int c = 0; c < VC; c++) {
        float a0 = sA[tn][SC + 3 * c + 0];
        float a1 = sA[tn][SC + 3 * c + 1];
        float a2 = sA[tn][SC + 3 * c + 2];
        float4 w = *reinterpret_cast<const float4*>(&W1sh[c][tc * 4]);
        avv[0]  = fmaf(a0, w.x, avv[0]);
        avv[1]  = fmaf(a1, w.x, avv[1]);
        avv[2]  = fmaf(a2, w.x, avv[2]);
        avv[3]  = fmaf(a0, w.y, avv[3]);
        avv[4]  = fmaf(a1, w.y, avv[4]);
        avv[5]  = fmaf(a2, w.y, avv[5]);
        avv[6]  = fmaf(a0, w.z, avv[6]);
        avv[7]  = fmaf(a1, w.z, avv[7]);
        avv[8]  = fmaf(a2, w.z, avv[8]);
        avv[9]  = fmaf(a0, w.w, avv[9]);
        avv[10] = fmaf(a1, w.w, avv[10]);
        avv[11] = fmaf(a2, w.w, avv[11]);
    }

    // ---- scale + LN stats over the 8 lanes sharing this tn ----
    float s1 = 0.f, s2 = 0.f;
#pragma unroll
    for (int q = 0; q < 8; q++) {
        as[q] *= ews;
        s1 += as[q];
        s2 += as[q] * as[q];
    }
#pragma unroll
    for (int o = 1; o < 8; o <<= 1) {
        s1 += __shfl_xor_sync(0xffffffffu, s1, o);
        s2 += __shfl_xor_sync(0xffffffffu, s2, o);
    }
    float mu  = s1 * (1.0f / SC);
    float var = s2 * (1.0f / SC) - mu * mu;
    float rstd = rsqrtf(var + 1e-5f);

    if (n < N) {
        float* orow = out + (size_t)n * DIMF;
        float x0 = (as[0] - mu) * rstd * gl.x + bl.x;
        float x1 = (as[1] - mu) * rstd * gl.y + bl.y;
        float x2 = (as[2] - mu) * rstd * gl.z + bl.z;
        float x3 = (as[3] - mu) * rstd * gl.w + bl.w;
        float4 r0 = make_float4(x0 / (1.f + expf(-x0)), x1 / (1.f + expf(-x1)),
                                x2 / (1.f + expf(-x2)), x3 / (1.f + expf(-x3)));
        float y0 = (as[4] - mu) * rstd * gh.x + bh.x;
        float y1 = (as[5] - mu) * rstd * gh.y + bh.y;
        float y2 = (as[6] - mu) * rstd * gh.z + bh.z;
        float y3 = (as[7] - mu) * rstd * gh.w + bh.w;
        float4 r1 = make_float4(y0 / (1.f + expf(-y0)), y1 / (1.f + expf(-y1)),
                                y2 / (1.f + expf(-y2)), y3 / (1.f + expf(-y3)));
        *reinterpret_cast<float4*>(orow + tc * 4)      = r0;
        *reinterpret_cast<float4*>(orow + 32 + tc * 4) = r1;
        float* ov = orow + SC + tc * 12;
        *reinterpret_cast<float4*>(ov + 0) =
            make_float4(avv[0] * ewv, avv[1] * ewv, avv[2] * ewv, avv[3] * ewv);
        *reinterpret_cast<float4*>(ov + 4) =
            make_float4(avv[4] * ewv, avv[5] * ewv, avv[6] * ewv, avv[7] * ewv);
        *reinterpret_cast<float4*>(ov + 8) =
            make_float4(avv[8] * ewv, avv[9] * ewv, avv[10] * ewv, avv[11] * ewv);
    }
}

extern "C" void kernel_launch(void* const* d_in, const int* in_sizes, int n_in,
                              void* d_out, int out_size) {
    const float* x       = (const float*)d_in[0];
    const float* pos     = (const float*)d_in[1];
    const int*   ei      = (const int*)d_in[2];   // int32 (JAX x64 disabled)
    // d_in[3] = edge_rand: unused (rotation cancels algebraically)
    const float* W0      = (const float*)d_in[4];
    const float* W1      = (const float*)d_in[5];
    const float* centers = (const float*)d_in[6];
    const float* widths  = (const float*)d_in[7];
    const float* pw      = (const float*)d_in[8];
    const float* pb      = (const float*)d_in[9];
    const float* gamma   = (const float*)d_in[10];
    const float* beta    = (const float*)d_in[11];
    float* out = (float*)d_out;

    int N = in_sizes[0] / DIMF;
    int E = in_sizes[2] / 2;

    cudaMemsetAsync(out, 0, (size_t)N * DIMF * sizeof(float), 0);
    k_build_table<<<(TBL + 255) / 256, 256>>>(centers, widths, pw, pb);
    k_scatter<<<(E + 31) / 32, 256>>>(ei, x, pos, out, E);
    k_finalize<<<(N + TILE_N - 1) / TILE_N, 256>>>(out, W0, W1, gamma, beta, N, E);
}